// round 16
// baseline (speedup 1.0000x reference)
#include <cuda_runtime.h>
#include <cuda_fp16.h>
#include <stdint.h>

#define D_MODEL  1024
#define D_HIDDEN 4096
#define NE       16
#define BTOK     32768
#define CAP      2560

// GEMM tiling (2 CTAs/SM, TK=64, 3-stage pipeline)
#define TM   128
#define TN   128
#define TK   64
#define NSTG 3
#define SA_HALVES 72            // padded row stride for A tile (128 x 64)
#define SB_HALVES 136           // padded row stride for B tile (64 x 128)
#define SA_BYTES  (128 * SA_HALVES * 2)   // 18432
#define SB_BYTES  (TK * SB_HALVES * 2)    // 17408
#define STG_BYTES (SA_BYTES + SB_BYTES)   // 35840
#define SMEM_TOTAL (NSTG * STG_BYTES)     // 107520

static __device__ __align__(256) __half g_xh  [(size_t)BTOK * D_MODEL];
static __device__ __align__(256) __half g_w1h [(size_t)NE * D_MODEL * D_HIDDEN];
static __device__ __align__(256) __half g_w2h [(size_t)NE * D_HIDDEN * D_MODEL];
static __device__ __align__(256) __half g_hbuf[(size_t)NE * CAP * D_HIDDEN];
static __device__ int g_eid[BTOK];
static __device__ int g_keep[BTOK];
static __device__ int g_counts[NE];
static __device__ int g_fill[NE];
static __device__ int g_list[NE * CAP];

// ---------------- small kernels ----------------
__global__ void zero_counts_kernel() {
    if (threadIdx.x < NE) { g_counts[threadIdx.x] = 0; g_fill[threadIdx.x] = 0; }
}

__global__ void cvt_w1_kernel(const float4* __restrict__ src) {
    __half2* dst = (__half2*)g_w1h;
    const int n4 = NE * D_MODEL * (D_HIDDEN / 4);
    for (int i = blockIdx.x * blockDim.x + threadIdx.x; i < n4; i += gridDim.x * blockDim.x) {
        float4 v = src[i];
        dst[2 * i + 0] = __floats2half2_rn(v.x, v.y);
        dst[2 * i + 1] = __floats2half2_rn(v.z, v.w);
    }
}
__global__ void cvt_w2_kernel(const float4* __restrict__ src) {
    __half2* dst = (__half2*)g_w2h;
    const int n4 = NE * D_MODEL * (D_HIDDEN / 4);
    for (int i = blockIdx.x * blockDim.x + threadIdx.x; i < n4; i += gridDim.x * blockDim.x) {
        float4 v = src[i];
        dst[2 * i + 0] = __floats2half2_rn(v.x, v.y);
        dst[2 * i + 1] = __floats2half2_rn(v.z, v.w);
    }
}

// one warp per TWO tokens; fp32 logits (argmax must match reference).
__global__ void gating_kernel(const float4* __restrict__ x4, const float4* __restrict__ gw4) {
    extern __shared__ float4 sgw[];   // 16 x 256 float4 = 64 KB
    for (int i = threadIdx.x; i < NE * (D_MODEL / 4); i += blockDim.x) sgw[i] = gw4[i];
    __syncthreads();

    const int warp = threadIdx.x >> 5, lane = threadIdx.x & 31;
    const int t0 = blockIdx.x * 16 + warp * 2;
    const int t1 = t0 + 1;
    const float4* xr0 = x4 + (size_t)t0 * (D_MODEL / 4);
    const float4* xr1 = x4 + (size_t)t1 * (D_MODEL / 4);
    __half2* xo0 = (__half2*)g_xh + (size_t)t0 * (D_MODEL / 2);
    __half2* xo1 = (__half2*)g_xh + (size_t)t1 * (D_MODEL / 2);

    float a0[NE], a1[NE];
#pragma unroll
    for (int e = 0; e < NE; ++e) { a0[e] = 0.f; a1[e] = 0.f; }
#pragma unroll
    for (int i = 0; i < 8; ++i) {
        int d = i * 32 + lane;
        float4 v0 = xr0[d];
        float4 v1 = xr1[d];
        xo0[d * 2 + 0] = __floats2half2_rn(v0.x, v0.y);
        xo0[d * 2 + 1] = __floats2half2_rn(v0.z, v0.w);
        xo1[d * 2 + 0] = __floats2half2_rn(v1.x, v1.y);
        xo1[d * 2 + 1] = __floats2half2_rn(v1.z, v1.w);
#pragma unroll
        for (int e = 0; e < NE; ++e) {
            float4 g = sgw[e * (D_MODEL / 4) + d];
            a0[e] += v0.x * g.x + v0.y * g.y + v0.z * g.z + v0.w * g.w;
            a1[e] += v1.x * g.x + v1.y * g.y + v1.z * g.z + v1.w * g.w;
        }
    }
#pragma unroll
    for (int e = 0; e < NE; ++e)
#pragma unroll
        for (int o = 16; o > 0; o >>= 1) {
            a0[e] += __shfl_xor_sync(0xffffffffu, a0[e], o);
            a1[e] += __shfl_xor_sync(0xffffffffu, a1[e], o);
        }

    if (lane == 0) {
        float mx = a0[0]; int am = 0;
#pragma unroll
        for (int e = 1; e < NE; ++e) if (a0[e] > mx) { mx = a0[e]; am = e; }
        g_eid[t0] = am;
        atomicAdd(&g_counts[am], 1);
        float mx1 = a1[0]; int am1 = 0;
#pragma unroll
        for (int e = 1; e < NE; ++e) if (a1[e] > mx1) { mx1 = a1[e]; am1 = e; }
        g_eid[t1] = am1;
        atomicAdd(&g_counts[am1], 1);
    }
}

__global__ void build_list_kernel() {
    int t = blockIdx.x * blockDim.x + threadIdx.x;
    if (t >= BTOK) return;
    int e = g_eid[t];
    int p = atomicAdd(&g_fill[e], 1);
    if (p < CAP) { g_list[e * CAP + p] = t; g_keep[t] = 1; }
    else         { g_keep[t] = 0; }
}

// copy x rows only for dropped tokens (none in the typical balanced case)
__global__ void copy_dropped_kernel(const float4* __restrict__ x4, float4* __restrict__ out4) {
    const int warp = threadIdx.x >> 5, lane = threadIdx.x & 31;
    const int t = blockIdx.x * 8 + warp;
    if (g_keep[t]) return;
    const float4* src = x4 + (size_t)t * (D_MODEL / 4);
    float4* dst = out4 + (size_t)t * (D_MODEL / 4);
#pragma unroll
    for (int i = 0; i < 8; ++i) dst[i * 32 + lane] = src[i * 32 + lane];
}

__global__ void stats_kernel(float* __restrict__ out, long long out_size) {
    int e = threadIdx.x;
    float c  = (e < NE) ? (float)g_counts[e] : 0.f;
    const float expc = (float)BTOK / NE;
    float d  = (e < NE) ? (c - expc) * (c - expc) : 0.f;
    float ov = (e < NE) ? fmaxf(c - (float)CAP, 0.f) : 0.f;
#pragma unroll
    for (int o = 16; o > 0; o >>= 1) {
        d  += __shfl_xor_sync(0xffffffffu, d,  o);
        ov += __shfl_xor_sync(0xffffffffu, ov, o);
    }
    if (threadIdx.x == 0) {
        float lb = (d / NE) / (expc * expc);
        if (out_size > (long long)BTOK * D_MODEL)     out[(long long)BTOK * D_MODEL]     = lb;
        if (out_size > (long long)BTOK * D_MODEL + 1) out[(long long)BTOK * D_MODEL + 1] = ov / (float)BTOK;
    }
}

// ---------------- mma helpers ----------------
__device__ __forceinline__ void ldsm4(uint32_t& r0, uint32_t& r1, uint32_t& r2, uint32_t& r3,
                                      const void* p) {
    uint32_t a = (uint32_t)__cvta_generic_to_shared(p);
    asm volatile("ldmatrix.sync.aligned.m8n8.x4.shared.b16 {%0,%1,%2,%3},[%4];"
                 : "=r"(r0), "=r"(r1), "=r"(r2), "=r"(r3) : "r"(a));
}
__device__ __forceinline__ void ldsm4t(uint32_t& r0, uint32_t& r1, uint32_t& r2, uint32_t& r3,
                                       const void* p) {
    uint32_t a = (uint32_t)__cvta_generic_to_shared(p);
    asm volatile("ldmatrix.sync.aligned.m8n8.x4.trans.shared.b16 {%0,%1,%2,%3},[%4];"
                 : "=r"(r0), "=r"(r1), "=r"(r2), "=r"(r3) : "r"(a));
}
__device__ __forceinline__ void mma16816(float* c, const uint32_t* a, const uint32_t* b) {
    asm volatile("mma.sync.aligned.m16n8k16.row.col.f32.f16.f16.f32 "
                 "{%0,%1,%2,%3},{%4,%5,%6,%7},{%8,%9},{%0,%1,%2,%3};"
                 : "+f"(c[0]), "+f"(c[1]), "+f"(c[2]), "+f"(c[3])
                 : "r"(a[0]), "r"(a[1]), "r"(a[2]), "r"(a[3]), "r"(b[0]), "r"(b[1]));
}
__device__ __forceinline__ void cp16(uint32_t dst, const void* src, int sz) {
    asm volatile("cp.async.cg.shared.global [%0], [%1], 16, %2;\n"
                 :: "r"(dst), "l"(src), "r"(sz));
}
__device__ __forceinline__ float gelu_tanh(float v) {
    float v3 = v * v * v;
    return 0.5f * v * (1.f + tanhf(0.7978845608028654f * (v + 0.044715f * v3)));
}

// ---------------- FFN GEMMs (cp.async 3-stage, TK=64, 128x128 tile, 2 CTAs/SM) ----------------
// MODE 0: H = gelu(gather(g_xh) @ W1[e] + b1) -> g_hbuf (f16)   N=4096 K=1024
// MODE 1: ye = g_hbuf[e] @ W2[e] + b2         -> out (scatter)  N=1024 K=4096
template <int MODE>
__global__ void __launch_bounds__(256, 2) moe_ffn_kernel(const float* __restrict__ bias,
                                                         float* __restrict__ out) {
    constexpr int N  = (MODE == 0) ? D_HIDDEN : D_MODEL;
    constexpr int K  = (MODE == 0) ? D_MODEL  : D_HIDDEN;
    constexpr int NK = K / TK;

    const int e  = blockIdx.z;
    const int m0 = blockIdx.y * TM;
    const int n0 = blockIdx.x * TN;
    const int me = min(g_counts[e], CAP);
    if (m0 >= me) return;

    extern __shared__ char dsm[];
    __shared__ int   s_tok[TM];
    __shared__ float s_bias[TN];

    const int tid = threadIdx.x;
    if (tid < TM) {
        int slot = m0 + tid;
        s_tok[tid] = (slot < me) ? g_list[e * CAP + slot] : -1;
    }
    if (tid < TN) s_bias[tid] = bias[e * N + n0 + tid];
    __syncthreads();

    const __half* Bsrc = ((MODE == 0) ? g_w1h : g_w2h) + (size_t)e * D_MODEL * D_HIDDEN;

    // ---- load geometry (256 threads, TK=64) ----
    // A tile: 128 rows x 8 chunks(16B) = 1024 -> 4 consecutive chunks/thread, 1 row/thread
    const int arow = tid >> 1;              // 0..127
    const int ach0 = (tid & 1) * 4;         // first chunk index (0 or 4)
    const uint32_t aDst = (uint32_t)arow * (SA_HALVES * 2) + (uint32_t)ach0 * 16;
    const __half* aSrc;
    int aSz;
    if (MODE == 0) {
        int tok = s_tok[arow];
        aSrc = g_xh + ((tok >= 0) ? ((size_t)tok * D_MODEL) : 0) + ach0 * 8;
        aSz  = (tok >= 0) ? 16 : 0;
    } else {
        aSrc = g_hbuf + ((size_t)e * CAP + m0 + arow) * D_HIDDEN + ach0 * 8;
        aSz  = 16;
    }
    // B tile: 64 rows x 16 chunks = 1024 -> 4 rows/thread (brow + 16q)
    const int brow = tid >> 4, bch = tid & 15;
    const __half* bSrc = Bsrc + (size_t)brow * N + n0 + bch * 8;
    const uint32_t bDst = (uint32_t)brow * (SB_HALVES * 2) + (uint32_t)bch * 16;

    uint32_t smemBase = (uint32_t)__cvta_generic_to_shared(dsm);

    auto load_stage = [&](int kt, int s) {
        uint32_t aS = smemBase + (uint32_t)s * STG_BYTES;
        uint32_t bS = aS + SA_BYTES;
        int ko = kt * TK;
#pragma unroll
        for (int c = 0; c < 4; ++c)
            cp16(aS + aDst + (uint32_t)c * 16, aSrc + ko + c * 8, aSz);
#pragma unroll
        for (int q = 0; q < 4; ++q)
            cp16(bS + bDst + (uint32_t)(q * 16) * (SB_HALVES * 2),
                 bSrc + (size_t)(ko + q * 16) * N, 16);
        asm volatile("cp.async.commit_group;\n");
    };

    int sl = 0;
#pragma unroll
    for (int kt = 0; kt < NSTG - 1; ++kt) {
        load_stage(kt, sl);
        sl = (sl == NSTG - 1) ? 0 : sl + 1;
    }

    // ---- compute geometry: 8 warps, warp tile 64 rows x 32 cols ----
    const int wid = tid >> 5, lane = tid & 31;
    const int wr = wid & 1, wc = wid >> 1;              // wr: 0..1, wc: 0..3
    const int lrow = lane & 15, lkh = (lane >> 4) << 3;

    float acc[4][4][4];
#pragma unroll
    for (int mi = 0; mi < 4; ++mi)
#pragma unroll
        for (int nj = 0; nj < 4; ++nj)
#pragma unroll
            for (int q = 0; q < 4; ++q) acc[mi][nj][q] = 0.f;

    int sc = 0;
#pragma unroll 1
    for (int kt = 0; kt < NK; ++kt) {
        asm volatile("cp.async.wait_group %0;\n" :: "n"(NSTG - 2));
        __syncthreads();   // protects reuse of the stage being overwritten below

        int ktn = kt + NSTG - 1;
        if (ktn < NK) {
            load_stage(ktn, sl);
            sl = (sl == NSTG - 1) ? 0 : sl + 1;
        } else {
            // keep commit-group cadence so wait_group(NSTG-2) still implies
            // the compute stage's group has retired (oldest-first retirement)
            asm volatile("cp.async.commit_group;\n");
        }

        const __half* sA = (const __half*)(dsm + (size_t)sc * STG_BYTES);
        const __half* sB = (const __half*)(dsm + (size_t)sc * STG_BYTES + SA_BYTES);
        sc = (sc == NSTG - 1) ? 0 : sc + 1;

#pragma unroll
        for (int kk = 0; kk < 4; ++kk) {
            const int ks = kk * 16;
            uint32_t af[4][4];
#pragma unroll
            for (int mi = 0; mi < 4; ++mi)
                ldsm4(af[mi][0], af[mi][1], af[mi][2], af[mi][3],
                      sA + (wr * 64 + mi * 16 + lrow) * SA_HALVES + ks + lkh);
            uint32_t bf[4][2];
#pragma unroll
            for (int nq = 0; nq < 2; ++nq) {
                uint32_t r0, r1, r2, r3;
                ldsm4t(r0, r1, r2, r3,
                       sB + (ks + lrow) * SB_HALVES + wc * 32 + nq * 16 + lkh);
                bf[nq * 2][0] = r0; bf[nq * 2][1] = r1;
                bf[nq * 2 + 1][0] = r2; bf[nq * 2 + 1][1] = r3;
            }
#pragma unroll
            for (int mi = 0; mi < 4; ++mi)
#pragma unroll
                for (int nj = 0; nj < 4; ++nj)
                    mma16816(acc[mi][nj], af[mi], bf[nj]);
        }
    }
    asm volatile("cp.async.wait_group 0;\n");

    // ---- epilogue ----
#pragma unroll
    for (int mi = 0; mi < 4; ++mi) {
        const int r0 = wr * 64 + mi * 16 + (lane >> 2);
#pragma unroll
        for (int nj = 0; nj < 4; ++nj) {
            const int cl = wc * 32 + nj * 8 + (lane & 3) * 2;   // local col in [0,128)
            if (MODE == 0) {
                float bb0 = s_bias[cl], bb1 = s_bias[cl + 1];
                __half* hb = g_hbuf + ((size_t)e * CAP + m0) * D_HIDDEN + n0 + cl;
                float v0 = gelu_tanh(acc[mi][nj][0] + bb0);
                float v1 = gelu_tanh(acc[mi][nj][1] + bb1);
                float v2 = gelu_tanh(acc[mi][nj][2] + bb0);
                float v3 = gelu_tanh(acc[mi][nj][3] + bb1);
                *(__half2*)(hb + (size_t)r0 * D_HIDDEN)       = __floats2half2_rn(v0, v1);
                *(__half2*)(hb + (size_t)(r0 + 8) * D_HIDDEN) = __floats2half2_rn(v2, v3);
            } else {
                float bb0 = s_bias[cl], bb1 = s_bias[cl + 1];
                int tok0 = s_tok[r0], tok1 = s_tok[r0 + 8];
                if (tok0 >= 0) {
                    float2 v; v.x = acc[mi][nj][0] + bb0; v.y = acc[mi][nj][1] + bb1;
                    *(float2*)(out + (size_t)tok0 * D_MODEL + n0 + cl) = v;
                }
                if (tok1 >= 0) {
                    float2 v; v.x = acc[mi][nj][2] + bb0; v.y = acc[mi][nj][3] + bb1;
                    *(float2*)(out + (size_t)tok1 * D_MODEL + n0 + cl) = v;
                }
            }
        }
    }
}

// ---------------- launch ----------------
extern "C" void kernel_launch(void* const* d_in, const int* in_sizes, int n_in,
                              void* d_out, int out_size) {
    const float* x  = (const float*)d_in[0];
    const float* gw = (const float*)d_in[1];
    const float* w1 = (const float*)d_in[2];
    const float* b1 = (const float*)d_in[3];
    const float* w2 = (const float*)d_in[4];
    const float* b2 = (const float*)d_in[5];
    float*       out = (float*)d_out;

    zero_counts_kernel<<<1, 32>>>();
    cvt_w1_kernel<<<2048, 256>>>((const float4*)w1);
    cvt_w2_kernel<<<2048, 256>>>((const float4*)w2);

    cudaFuncSetAttribute(gating_kernel, cudaFuncAttributeMaxDynamicSharedMemorySize, 65536);
    gating_kernel<<<BTOK / 16, 256, 65536>>>((const float4*)x, (const float4*)gw);

    build_list_kernel<<<BTOK / 256, 256>>>();
    stats_kernel<<<1, 32>>>(out, (long long)out_size);
    copy_dropped_kernel<<<BTOK / 8, 256>>>((const float4*)x, (float4*)out);

    cudaFuncSetAttribute(moe_ffn_kernel<0>, cudaFuncAttributeMaxDynamicSharedMemorySize, SMEM_TOTAL);
    cudaFuncSetAttribute(moe_ffn_kernel<1>, cudaFuncAttributeMaxDynamicSharedMemorySize, SMEM_TOTAL);
    moe_ffn_kernel<0><<<dim3(D_HIDDEN / TN, CAP / TM, NE), 256, SMEM_TOTAL>>>(b1, out);
    moe_ffn_kernel<1><<<dim3(D_MODEL / TN, CAP / TM, NE), 256, SMEM_TOTAL>>>(b2, out);
}